// round 16
// baseline (speedup 1.0000x reference)
#include <cuda_runtime.h>
#include <cuda_bf16.h>
#include <math.h>
#include <stdint.h>

// ---------------- problem constants ----------------
#define T_TOK   4096
#define HID     4096
#define NH      32
#define NKV     8
#define HD      128
#define INTER   14336
#define BATCH   4
#define SEQ     1024
#define QKV_N   6144            // (NH + 2*NKV) * HD
#define UP_N    28672           // 2 * INTER
#define LIMIT   20.0f
#define LN_EPS  1e-5f
#define ATTN_SCALE 0.08838834764831845f  // 128^-0.5

// ---------------- device scratch (no allocations allowed) ----------------
__device__ float g_h[(size_t)T_TOK * HID];
__device__ float g_qkv[(size_t)T_TOK * QKV_N];
// split-bf16 qkv planes (Q pre-scaled by ATTN_SCALE)
__device__ __nv_bfloat16 g_qkvh[(size_t)T_TOK * QKV_N];
__device__ __nv_bfloat16 g_qkvl[(size_t)T_TOK * QKV_N];
// split-bf16 activation planes
__device__ __nv_bfloat16 g_normh[(size_t)T_TOK * HID];
__device__ __nv_bfloat16 g_norml[(size_t)T_TOK * HID];
__device__ __nv_bfloat16 g_ctxh[(size_t)T_TOK * HID];
__device__ __nv_bfloat16 g_ctxl[(size_t)T_TOK * HID];
__device__ __nv_bfloat16 g_acth[(size_t)T_TOK * INTER];
__device__ __nv_bfloat16 g_actl[(size_t)T_TOK * INTER];
// split-bf16 TRANSPOSED weight planes: [N][K]
__device__ __nv_bfloat16 g_wqkvh[(size_t)QKV_N * HID];
__device__ __nv_bfloat16 g_wqkvl[(size_t)QKV_N * HID];
__device__ __nv_bfloat16 g_woh[(size_t)HID * HID];
__device__ __nv_bfloat16 g_wol[(size_t)HID * HID];
__device__ __nv_bfloat16 g_wuph[(size_t)UP_N * HID];
__device__ __nv_bfloat16 g_wupl[(size_t)UP_N * HID];
__device__ __nv_bfloat16 g_wdnh[(size_t)HID * INTER];
__device__ __nv_bfloat16 g_wdnl[(size_t)HID * INTER];

// =======================================================================
// Helpers
// =======================================================================
__device__ __forceinline__ uint32_t swz128(uint32_t o) {
    return o ^ ((o >> 3) & 0x70);
}
__device__ __forceinline__ uint32_t smem_u32(const void* p) {
    uint32_t a;
    asm("{ .reg .u64 t; cvta.to.shared.u64 t, %1; cvt.u32.u64 %0, t; }"
        : "=r"(a) : "l"(p));
    return a;
}
__device__ __forceinline__ void cp16(uint32_t s, const void* g) {
    asm volatile("cp.async.cg.shared.global [%0], [%1], 16;" :: "r"(s), "l"(g));
}
#define CP_COMMIT() asm volatile("cp.async.commit_group;" ::: "memory")
#define CP_WAIT1()  asm volatile("cp.async.wait_group 1;" ::: "memory")
#define CP_WAIT0()  asm volatile("cp.async.wait_group 0;" ::: "memory")

#define MBAR_INIT(mb, cnt) \
    asm volatile("mbarrier.init.shared.b64 [%0], %1;" :: "r"(mb), "r"((uint32_t)(cnt)) : "memory")
#define MBAR_ARRIVE(mb) \
    asm volatile("mbarrier.arrive.shared.b64 _, [%0];" :: "r"(mb) : "memory")

__device__ __forceinline__ void mbar_wait(uint32_t mb, uint32_t parity) {
    asm volatile(
        "{\n\t"
        ".reg .pred P1;\n\t"
        "LAB_WAIT_%=:\n\t"
        "mbarrier.try_wait.parity.acquire.cta.shared::cta.b64 P1, [%0], %1, 0x989680;\n\t"
        "@P1 bra.uni LAB_DONE_%=;\n\t"
        "bra.uni LAB_WAIT_%=;\n\t"
        "LAB_DONE_%=:\n\t"
        "}"
        :: "r"(mb), "r"(parity) : "memory");
}

__device__ __forceinline__ void ldsm4(uint32_t* r, uint32_t addr) {
    asm volatile("ldmatrix.sync.aligned.m8n8.x4.shared.b16 {%0,%1,%2,%3}, [%4];"
                 : "=r"(r[0]), "=r"(r[1]), "=r"(r[2]), "=r"(r[3])
                 : "r"(addr));
}
__device__ __forceinline__ void ldsm4t(uint32_t* r, uint32_t addr) {
    asm volatile("ldmatrix.sync.aligned.m8n8.x4.trans.shared.b16 {%0,%1,%2,%3}, [%4];"
                 : "=r"(r[0]), "=r"(r[1]), "=r"(r[2]), "=r"(r[3])
                 : "r"(addr));
}

__device__ __forceinline__ float gegelu_pair(float a_in, float lin_in) {
    float a   = fminf(a_in, LIMIT);
    float lin = fminf(fmaxf(lin_in, -LIMIT), LIMIT);
    float sig = 1.0f / (1.0f + __expf(-1.702f * a));
    return a * sig * (lin + 1.0f);
}
__device__ __forceinline__ void split1(float v, __nv_bfloat16& h, __nv_bfloat16& l) {
    h = __float2bfloat16(v);
    l = __float2bfloat16(v - __bfloat162float(h));
}
__device__ __forceinline__ void split2w(float a, float b, uint32_t& hw, uint32_t& lw) {
    __nv_bfloat162 hv, lv;
    hv.x = __float2bfloat16(a);
    hv.y = __float2bfloat16(b);
    lv.x = __float2bfloat16(a - __bfloat162float(hv.x));
    lv.y = __float2bfloat16(b - __bfloat162float(hv.y));
    hw = *(uint32_t*)&hv;
    lw = *(uint32_t*)&lv;
}
__device__ __forceinline__ uint32_t packbf2(float a, float b) {
    __nv_bfloat162 v;
    v.x = __float2bfloat16(a);
    v.y = __float2bfloat16(b);
    return *(uint32_t*)&v;
}

__device__ __forceinline__ void mma16816(float* c, const uint32_t* a,
                                         const uint32_t* b) {
    asm volatile(
        "mma.sync.aligned.m16n8k16.row.col.f32.bf16.bf16.f32 "
        "{%0,%1,%2,%3}, {%4,%5,%6,%7}, {%8,%9}, {%0,%1,%2,%3};"
        : "+f"(c[0]), "+f"(c[1]), "+f"(c[2]), "+f"(c[3])
        : "r"(a[0]), "r"(a[1]), "r"(a[2]), "r"(a[3]), "r"(b[0]), "r"(b[1]));
}

// =======================================================================
// Weight transpose + split: w [K][N] fp32 -> th, tl [N][K] bf16.
// =======================================================================
__global__ void wsplit_kernel(const float* __restrict__ w,
                              __nv_bfloat16* __restrict__ th,
                              __nv_bfloat16* __restrict__ tl,
                              int K, int N) {
    __shared__ float s[64][33];
    const int k0 = blockIdx.y * 64, n0 = blockIdx.x * 32;
    const int tx = threadIdx.x, ty = threadIdx.y;
#pragma unroll
    for (int i = 0; i < 8; i++) {
        int k = ty + i * 8;
        s[k][tx] = w[(size_t)(k0 + k) * N + n0 + tx];
    }
    __syncthreads();
#pragma unroll
    for (int j = 0; j < 4; j++) {
        int n = ty * 4 + j;
        uint32_t hw, lw;
        split2w(s[tx * 2][n], s[tx * 2 + 1][n], hw, lw);
        size_t o = (size_t)(n0 + n) * K + k0 + tx * 2;
        *(uint32_t*)&th[o] = hw;
        *(uint32_t*)&tl[o] = lw;
    }
}

// =======================================================================
// LayerNorm (optionally fused residual add); writes split-bf16 planes
// =======================================================================
__global__ void ln_kernel(const float* __restrict__ x,
                          const float* __restrict__ res,
                          const float* __restrict__ w,
                          const float* __restrict__ b,
                          float* __restrict__ h_out,
                          __nv_bfloat16* __restrict__ nh,
                          __nv_bfloat16* __restrict__ nl) {
    __shared__ float sred[256];
    const int row = blockIdx.x;
    const int tid = threadIdx.x;
    const size_t base = (size_t)row * HID;

    float vals[16];
    float s = 0.f, s2 = 0.f;
#pragma unroll
    for (int i = 0; i < 16; i++) {
        int c = i * 256 + tid;
        float v = x[base + c];
        if (res)   v += res[base + c];
        if (h_out) h_out[base + c] = v;
        vals[i] = v;
        s += v;
        s2 += v * v;
    }
    sred[tid] = s; __syncthreads();
    for (int off = 128; off > 0; off >>= 1) {
        if (tid < off) sred[tid] += sred[tid + off];
        __syncthreads();
    }
    float mean = sred[0] * (1.0f / HID);
    __syncthreads();
    sred[tid] = s2; __syncthreads();
    for (int off = 128; off > 0; off >>= 1) {
        if (tid < off) sred[tid] += sred[tid + off];
        __syncthreads();
    }
    float var = sred[0] * (1.0f / HID) - mean * mean;
    float rstd = rsqrtf(var + LN_EPS);

#pragma unroll
    for (int i = 0; i < 16; i++) {
        int c = i * 256 + tid;
        float v = (vals[i] - mean) * rstd * w[c] + b[c];
        __nv_bfloat16 h, l;
        split1(v, h, l);
        nh[base + c] = h;
        nl[base + c] = l;
    }
}

// =======================================================================
// RoPE (in-place on q and k parts of qkv)
// =======================================================================
__global__ void rope_kernel(float* __restrict__ qkv,
                            const float* __restrict__ cosp,
                            const float* __restrict__ sinp) {
    const int t = blockIdx.x;
    const float* cr = cosp + (size_t)t * 64;
    const float* sr = sinp + (size_t)t * 64;
    for (int i = threadIdx.x; i < (NH + NKV) * 64; i += 256) {
        int h = i >> 6;
        int d = i & 63;
        size_t base = (size_t)t * QKV_N +
                      (h < NH ? (size_t)h * HD : (size_t)NH * HD + (size_t)(h - NH) * HD);
        float c = cr[d], s = sr[d];
        float x1 = qkv[base + d];
        float x2 = qkv[base + 64 + d];
        qkv[base + d]      = x1 * c - x2 * s;
        qkv[base + 64 + d] = x2 * c + x1 * s;
    }
}

// =======================================================================
// QKV split: fp32 qkv -> bf16 hi/lo planes. Q part pre-scaled by ATTN_SCALE.
// =======================================================================
__global__ void qkvsplit_kernel(const float* __restrict__ qkv,
                                __nv_bfloat16* __restrict__ qh,
                                __nv_bfloat16* __restrict__ ql) {
    const size_t base = (size_t)blockIdx.x * QKV_N;
#pragma unroll
    for (int i = 0; i < QKV_N / 256; i++) {
        int c = i * 256 + threadIdx.x;
        float v = qkv[base + c];
        if (c < NH * HD) v *= ATTN_SCALE;
        __nv_bfloat16 h, l;
        split1(v, h, l);
        qh[base + c] = h;
        ql[base + c] = l;
    }
}

// =======================================================================
// HMMA flash attention (unchanged from R14). Block = 64 q-rows x 1 head.
// =======================================================================
#define ATT_SMEM (32768 + 2 * 65536)

__global__ void __launch_bounds__(128, 1) attn_kernel(
        const __nv_bfloat16* __restrict__ qph,
        const __nv_bfloat16* __restrict__ qpl,
        __nv_bfloat16* __restrict__ ctxh,
        __nv_bfloat16* __restrict__ ctxl) {
    extern __shared__ __align__(1024) char smem[];
    const uint32_t sb = smem_u32(smem);
    const int qt  = blockIdx.x;
    const int hq  = blockIdx.y;
    const int b   = blockIdx.z;
    const int tid  = threadIdx.x;
    const int wid  = tid >> 5;
    const int lane = tid & 31;
    const int gid = lane >> 2, tg = lane & 3;
    const int matq = lane >> 3, rowin = lane & 7;

    const int kvh  = hq >> 2;
    const int koff = NH * HD + kvh * HD;
    const int voff = NH * HD + NKV * HD + kvh * HD;
    const size_t bS = (size_t)b * SEQ;

    const uint32_t a_row = (uint32_t)((matq & 1) * 8 + rowin);
    const uint32_t a_ch  = (uint32_t)(matq >> 1);
    const uint32_t b_row = (uint32_t)((matq >> 1) * 8 + rowin);
    const uint32_t b_ch  = (uint32_t)(matq & 1);
    const uint32_t v_row = (uint32_t)((matq & 1) * 8 + rowin);
    const uint32_t v_ch  = (uint32_t)(matq >> 1);

#pragma unroll
    for (int q = 0; q < 16; q++) {
        int idx = q * 128 + tid;
        int c = idx & 7, r = (idx >> 3) & 63, h2 = (idx >> 9) & 1, sel = idx >> 10;
        const __nv_bfloat16* src = sel ? qpl : qph;
        uint32_t dst = sb + sel * 16384 + h2 * 8192 + swz128((uint32_t)(r * 128 + c * 16));
        cp16(dst, src + (bS + qt * 64 + r) * QKV_N + hq * HD + h2 * 64 + c * 8);
    }
    {
        uint32_t bb = sb + 32768;
#pragma unroll
        for (int q = 0; q < 32; q++) {
            int idx = q * 128 + tid;
            int c = idx & 7, r = (idx >> 3) & 63, h2 = (idx >> 9) & 1, sel = idx >> 10;
            const __nv_bfloat16* src = (sel & 1) ? qpl : qph;
            int colb = (sel < 2 ? koff : voff) + h2 * 64 + c * 8;
            uint32_t dst = bb + sel * 16384 + h2 * 8192 + swz128((uint32_t)(r * 128 + c * 16));
            cp16(dst, src + (bS + r) * QKV_N + colb);
        }
    }
    CP_COMMIT();

    float m0 = -1e30f, m1 = -1e30f, l0 = 0.f, l1 = 0.f;
    float ctx[16][4];
#pragma unroll
    for (int j = 0; j < 16; j++)
#pragma unroll
        for (int q = 0; q < 4; q++) ctx[j][q] = 0.f;

    const int qg0 = qt * 64 + wid * 16 + gid;
    const int qg1 = qg0 + 8;

#pragma unroll 1
    for (int kt = 0; kt <= qt; kt++) {
        CP_WAIT0();
        __syncthreads();
        const uint32_t bb = sb + 32768 + (kt & 1) * 65536;
        if (kt < qt) {
            uint32_t nb = sb + 32768 + ((kt + 1) & 1) * 65536;
#pragma unroll
            for (int q = 0; q < 32; q++) {
                int idx = q * 128 + tid;
                int c = idx & 7, r = (idx >> 3) & 63, h2 = (idx >> 9) & 1, sel = idx >> 10;
                const __nv_bfloat16* src = (sel & 1) ? qpl : qph;
                int colb = (sel < 2 ? koff : voff) + h2 * 64 + c * 8;
                uint32_t dst = nb + sel * 16384 + h2 * 8192 +
                               swz128((uint32_t)(r * 128 + c * 16));
                cp16(dst, src + (bS + (kt + 1) * 64 + r) * QKV_N + colb);
            }
            CP_COMMIT();
        }

        float sc[8][4];
#pragma unroll
        for (int j = 0; j < 8; j++)
#pragma unroll
            for (int q = 0; q < 4; q++) sc[j][q] = 0.f;

#pragma unroll
        for (int h2 = 0; h2 < 2; h2++) {
#pragma unroll
            for (int kc = 0; kc < 4; kc++) {
                uint32_t arow = (uint32_t)(wid * 16) + a_row;
                uint32_t offa = h2 * 8192 + swz128(arow * 128 + (2 * kc + a_ch) * 16);
                uint32_t qhf[4], qlf[4];
                ldsm4(qhf, sb + offa);
                ldsm4(qlf, sb + 16384 + offa);
                uint32_t khf[8][2], klf[8][2];
#pragma unroll
                for (int g = 0; g < 4; g++) {
                    uint32_t rowb = (uint32_t)(g * 16) + b_row;
                    uint32_t offb = h2 * 8192 + swz128(rowb * 128 + (2 * kc + b_ch) * 16);
                    ldsm4(&khf[2 * g][0], bb + offb);
                    ldsm4(&klf[2 * g][0], bb + 16384 + offb);
                }
#pragma unroll
                for (int j = 0; j < 8; j++) mma16816(sc[j], qhf, khf[j]);
#pragma unroll
                for (int j = 0; j < 8; j++) mma16816(sc[j], qhf, klf[j]);
#pragma unroll
                for (int j = 0; j < 8; j++) mma16816(sc[j], qlf, khf[j]);
            }
        }

        if (kt == qt) {
#pragma unroll
            for (int j = 0; j < 8; j++) {
                int k0 = kt * 64 + j * 8 + tg * 2;
                if (k0     > qg0) sc[j][0] = -1e30f;
                if (k0 + 1 > qg0) sc[j][1] = -1e30f;
                if (k0     > qg1) sc[j][2] = -1e30f;
                if (k0 + 1 > qg1) sc[j][3] = -1e30f;
            }
        }

        float rm0 = -1e30f, rm1 = -1e30f;
#pragma unroll
        for (int j = 0; j < 8; j++) {
            rm0 = fmaxf(rm0, fmaxf(sc[j][0], sc[j][1]));
            rm1 = fmaxf(rm1, fmaxf(sc[j][2], sc[j][3]));
        }
        rm0 = fmaxf(rm0, __shfl_xor_sync(0xffffffffu, rm0, 1));
        rm0 = fmaxf(rm0, __shfl_xor_sync(0xffffffffu, rm0, 2));
        rm1 = fmaxf(rm1, __shfl_xor_sync(0xffffffffu, rm1, 1));
        rm1 = fmaxf(rm1, __shfl_xor_sync(0xffffffffu, rm1, 2));
        float mn0 = fmaxf(m0, rm0), mn1 = fmaxf(m1, rm1);
        float sf0 = __expf(m0 - mn0), sf1 = __expf(m1 - mn1);
        m0 = mn0; m1 = mn1;
        float ps0 = 0.f, ps1 = 0.f;
#pragma unroll
        for (int j = 0; j < 8; j++) {
            sc[j][0] = __expf(sc[j][0] - mn0);
            sc[j][1] = __expf(sc[j][1] - mn0);
            sc[j][2] = __expf(sc[j][2] - mn1);
            sc[j][3] = __expf(sc[j][3] - mn1);
            ps0 += sc[j][0] + sc[j][1];
            ps1 += sc[j][2] + sc[j][3];
        }
        ps0 += __shfl_xor_sync(0xffffffffu, ps0, 1);
        ps0 += __shfl_xor_sync(0xffffffffu, ps0, 2);
        ps1 += __shfl_xor_sync(0xffffffffu, ps1, 1);
        ps1 += __shfl_xor_sync(0xffffffffu, ps1, 2);
        l0 = l0 * sf0 + ps0;
        l1 = l1 * sf1 + ps1;
#pragma unroll
        for (int j = 0; j < 16; j++) {
            ctx[j][0] *= sf0; ctx[j][1] *= sf0;
            ctx[j][2] *= sf1; ctx[j][3] *= sf1;
        }

        uint32_t pah[4][4], pal[4][4];
#pragma unroll
        for (int t = 0; t < 4; t++) {
#pragma unroll
            for (int half = 0; half < 2; half++) {
                int j = 2 * t + half;
                float p0 = sc[j][0], p1 = sc[j][1], p2 = sc[j][2], p3 = sc[j][3];
                __nv_bfloat16 h0 = __float2bfloat16(p0), h1 = __float2bfloat16(p1);
                __nv_bfloat16 h2 = __float2bfloat16(p2), h3 = __float2bfloat16(p3);
                pah[t][half * 2 + 0] = ((uint32_t)*(uint16_t*)&h1 << 16) | *(uint16_t*)&h0;
                pah[t][half * 2 + 1] = ((uint32_t)*(uint16_t*)&h3 << 16) | *(uint16_t*)&h2;
                pal[t][half * 2 + 0] = packbf2(p0 - __bfloat162float(h0),
                                               p1 - __bfloat162float(h1));
                pal[t][half * 2 + 1] = packbf2(p2 - __bfloat162float(h2),
                                               p3 - __bfloat162float(h3));
            }
        }

#pragma unroll
        for (int t = 0; t < 4; t++) {
#pragma unroll
            for (int g = 0; g < 8; g++) {
                uint32_t vr = (uint32_t)(t * 16) + v_row;
                uint32_t vc = (uint32_t)((g & 3) * 2) + v_ch;
                uint32_t offv = (g >> 2) * 8192 + swz128(vr * 128 + vc * 16);
                uint32_t vhf[4], vlf[4];
                ldsm4t(vhf, bb + 32768 + offv);
                ldsm4t(vlf, bb + 49152 + offv);
                mma16816(ctx[2 * g],     pah[t], vhf);
                mma16816(ctx[2 * g],     pah[t], vlf);
                mma16816(ctx[2 * g],     pal[t], vhf);
                mma16816(ctx[2 * g + 1], pah[t], vhf + 2);
                mma16816(ctx[2 * g + 1], pah[t], vlf + 2);
                mma16816(ctx[2 * g + 1], pal[t], vhf + 2);
            }
        }
        __syncthreads();
    }

    float inv0 = 1.0f / l0, inv1 = 1.0f / l1;
    const size_t t0 = (bS + qt * 64 + wid * 16 + gid) * (size_t)HID + hq * HD;
    const size_t t1 = t0 + (size_t)8 * HID;
#pragma unroll
    for (int j = 0; j < 16; j++) {
        int col = j * 8 + tg * 2;
        float v0 = ctx[j][0] * inv0, v1 = ctx[j][1] * inv0;
        float v2 = ctx[j][2] * inv1, v3 = ctx[j][3] * inv1;
        uint32_t hw, lw;
        split2w(v0, v1, hw, lw);
        *(uint32_t*)&ctxh[t0 + col] = hw;
        *(uint32_t*)&ctxl[t0 + col] = lw;
        split2w(v2, v3, hw, lw);
        *(uint32_t*)&ctxh[t1 + col] = hw;
        *(uint32_t*)&ctxl[t1 + col] = lw;
    }
}

// =======================================================================
// Warp-specialized HMMA split-bf16 GEMM. CTA 128x256, K-chunk 64, PIPE=2.
// 320 threads: warps 0-7 consumers (m32 x n128), warps 8-9 producers.
// mbarriers at sb: full0@0 full1@8 empty0@16 empty1@24; stages at sb+1024.
// Producer: wait empty -> 96 cp16 -> commit -> (lagged) wait_group -> arrive full.
// Consumer: wait full -> 4 ks x (12 LDSM + 48 MMA) -> arrive empty. No bar.sync.
// EPI 0: C=acc+bias ; EPI 1: C=acc+addsrc ; EPI 2: planes=gegelu(acc+bias)
// =======================================================================
#define STAGE_BYTES 98304
#define GEMM_SMEM_BYTES (1024 + 2 * STAGE_BYTES)

template <int EPI>
__global__ void __launch_bounds__(320, 1) hgemm(const __nv_bfloat16* __restrict__ Ah,
                                                const __nv_bfloat16* __restrict__ Al,
                                                const __nv_bfloat16* __restrict__ Bh,
                                                const __nv_bfloat16* __restrict__ Bl,
                                                const float* __restrict__ bias,
                                                const float* __restrict__ addsrc,
                                                float* __restrict__ C,
                                                __nv_bfloat16* __restrict__ Ch,
                                                __nv_bfloat16* __restrict__ Cl,
                                                int N, int K, int tiles_n) {
    extern __shared__ __align__(1024) char smem[];
    const uint32_t sb = smem_u32(smem);
    const int tid = threadIdx.x;

    // supertile rasterization: groups of 8 bm rows for L2 reuse
    const int lin = blockIdx.x;
    const int per = 8 * tiles_n;
    const int grp = lin / per, rem = lin % per;
    const int bm = grp * 8 + (rem & 7);
    const int bn = rem >> 3;
    const int KT = K >> 6;

    if (tid == 0) {
        MBAR_INIT(sb + 0,  64);   // full[0]
        MBAR_INIT(sb + 8,  64);   // full[1]
        MBAR_INIT(sb + 16, 256);  // empty[0]
        MBAR_INIT(sb + 24, 256);  // empty[1]
    }
    __syncthreads();

    if (tid >= 256) {
        // ---------------- producer warps ----------------
        const int pt = tid - 256;   // 0..63
#pragma unroll 1
        for (int kt = 0; kt < KT; kt++) {
            // empty-wait: phase starts at 1 so first two waits pass
            mbar_wait(sb + 16 + (kt & 1) * 8, ((kt >> 1) & 1) ^ 1);
            const uint32_t st = sb + 1024 + (kt & 1) * STAGE_BYTES;
            // A: 2048 cp16 -> 32/thread
#pragma unroll
            for (int q = 0; q < 32; q++) {
                int idx = q * 64 + pt;
                int plane = idx >> 10, i = idx & 1023;
                int r = i >> 3, c = i & 7;
                uint32_t off = swz128((uint32_t)(r * 128 + c * 16));
                size_t ga = (size_t)(bm * 128 + r) * K + kt * 64 + c * 8;
                cp16(st + plane * 16384 + off, (plane ? Al : Ah) + ga);
            }
            // B: 4096 cp16 -> 64/thread
#pragma unroll
            for (int q = 0; q < 64; q++) {
                int idx = q * 64 + pt;
                int plane = idx >> 11, i = idx & 2047;
                int r = i >> 3, c = i & 7;
                uint32_t off = swz128((uint32_t)(r * 128 + c * 16));
                size_t gb = (size_t)(bn * 256 + r) * K + kt * 64 + c * 8;
                cp16(st + 32768 + plane * 32768 + off, (plane ? Bl : Bh) + gb);
            }
            CP_COMMIT();
            if (kt >= 1) {       // signal previous stage (its group retired)
                CP_WAIT1();
                MBAR_ARRIVE(sb + ((kt - 1) & 1) * 8);
            }
        }
        CP_WAIT0();
        MBAR_ARRIVE(sb + ((KT - 1) & 1) * 8);
        return;
    }

    // ---------------- consumer warps ----------------
    const int wid  = tid >> 5;
    const int lane = tid & 31;
    const int wm = (wid >> 1) * 32;
    const int wn = (wid & 1) * 128;
    const int gid = lane >> 2, tg = lane & 3;
    const int matq  = lane >> 3;
    const int rowin = lane & 7;
    const uint32_t a_row = (uint32_t)((matq & 1) * 8 + rowin);
    const uint32_t a_ch  = (uint32_t)(matq >> 1);
    const uint32_t b_row = (uint32_t)((matq >> 1) * 8 + rowin);
    const uint32_t b_ch  = (uint32_t)(matq & 1);

    float acc[2][16][4];
#pragma unroll
    for (int mi = 0; mi < 2; mi++)
#pragma unroll
        for (int ni = 0; ni < 16; ni++)
#pragma unroll
            for (int q = 0; q < 4; q++) acc[mi][ni][q] = 0.f;

#pragma unroll 1
    for (int kt = 0; kt < KT; kt++) {
        mbar_wait(sb + (kt & 1) * 8, (kt >> 1) & 1);   // full-wait (acquire)
        const uint32_t st = sb + 1024 + (kt & 1) * STAGE_BYTES;
#pragma unroll
        for (int ks = 0; ks < 4; ks++) {
            const uint32_t kc = (uint32_t)(ks * 2);
            uint32_t ahf[2][4], alf[2][4];
#pragma unroll
            for (int mi = 0; mi < 2; mi++) {
                uint32_t row = (uint32_t)(wm + mi * 16) + a_row;
                uint32_t off = swz128(row * 128 + (kc + a_ch) * 16);
                ldsm4(ahf[mi], st + off);
                ldsm4(alf[mi], st + 16384 + off);
            }
#pragma unroll
            for (int bh2 = 0; bh2 < 2; bh2++) {
                uint32_t bhf[8][2], blf[8][2];
#pragma unroll
                for (int q = 0; q < 4; q++) {
                    uint32_t row = (uint32_t)(wn + bh2 * 64 + q * 16) + b_row;
                    uint32_t off = swz128(row * 128 + (kc + b_ch) * 16);
                    ldsm4(&bhf[2 * q][0], st + 32768 + off);
                    ldsm4(&blf[2 * q][0], st + 65536 + off);
                }
#pragma unroll
                for (int mi = 0; mi < 2; mi++)
#pragma unroll
                    for (int ni = 0; ni < 8; ni++)
                        mma16816(acc[mi][bh2 * 8 + ni], ahf[mi], bhf[ni]);
#pragma unroll
                for (int mi = 0; mi < 2; mi++)
#pragma unroll
                    for (int ni = 0; ni < 8; ni++)
                        mma16816(acc[mi][bh2 * 8 + ni], ahf[mi], blf[ni]);
#pragma unroll
                for (int mi = 0; mi < 2; mi++)
#pragma unroll
                    for (int ni = 0; ni < 8; ni++)
                        mma16816(acc[mi][bh2 * 8 + ni], alf[mi], bhf[ni]);
            }
        }
        MBAR_ARRIVE(sb + 16 + (kt & 1) * 8);   // this thread done with slot
    }

    // epilogue (consumers only)
#pragma unroll
    for (int mi = 0; mi < 2; mi++) {
#pragma unroll
        for (int ni = 0; ni < 16; ni++) {
            int row0 = bm * 128 + wm + mi * 16 + gid;
            int row1 = row0 + 8;
            int col  = bn * 256 + wn + ni * 8 + tg * 2;
            float c0 = acc[mi][ni][0], c1 = acc[mi][ni][1];
            float c2 = acc[mi][ni][2], c3 = acc[mi][ni][3];
            if (EPI == 2) {
                float b0 = bias[col], b1 = bias[col + 1];
                float v0 = gegelu_pair(c0 + b0, c1 + b1);
                float v1 = gegelu_pair(c2 + b0, c3 + b1);
                size_t o0 = (size_t)row0 * (N >> 1) + (col >> 1);
                size_t o1 = (size_t)row1 * (N >> 1) + (col >> 1);
                __nv_bfloat16 h, l;
                split1(v0, h, l); Ch[o0] = h; Cl[o0] = l;
                split1(v1, h, l); Ch[o1] = h; Cl[o1] = l;
            } else if (EPI == 0) {
                float b0 = bias[col], b1 = bias[col + 1];
                *(float2*)(C + (size_t)row0 * N + col) = make_float2(c0 + b0, c1 + b1);
                *(float2*)(C + (size_t)row1 * N + col) = make_float2(c2 + b0, c3 + b1);
            } else {
                float2 a0 = *(const float2*)(addsrc + (size_t)row0 * N + col);
                float2 a1 = *(const float2*)(addsrc + (size_t)row1 * N + col);
                *(float2*)(C + (size_t)row0 * N + col) = make_float2(c0 + a0.x, c1 + a0.y);
                *(float2*)(C + (size_t)row1 * N + col) = make_float2(c2 + a1.x, c3 + a1.y);
            }
        }
    }
}

// =======================================================================
// launcher
// =======================================================================
extern "C" void kernel_launch(void* const* d_in, const int* in_sizes, int n_in,
                              void* d_out, int out_size) {
    const float* hs     = (const float*)d_in[0];
    const float* res    = (const float*)d_in[1];
    const float* cosp   = (const float*)d_in[2];
    const float* sinp   = (const float*)d_in[3];
    const float* w_qkv  = (const float*)d_in[5];
    const float* b_qkv  = (const float*)d_in[6];
    const float* w_o    = (const float*)d_in[7];
    const float* w_ln1  = (const float*)d_in[8];
    const float* b_ln1  = (const float*)d_in[9];
    const float* w_ln2  = (const float*)d_in[10];
    const float* b_ln2  = (const float*)d_in[11];
    const float* w_up   = (const float*)d_in[12];
    const float* b_up   = (const float*)d_in[13];
    const float* w_down = (const float*)d_in[14];
    const float* b_down = (const float*)d_in[15];

    float* out     = (float*)d_out;
    float* mlp_out = out;
    float* h2      = out + (size_t)T_TOK * HID;

    float *p_h, *p_qkv;
    __nv_bfloat16 *p_qh, *p_ql, *p_nh, *p_nl, *p_ch, *p_cl, *p_ah, *p_al;
    __nv_bfloat16 *p_wqh, *p_wql, *p_woh, *p_wol, *p_wuh, *p_wul, *p_wdh, *p_wdl;
    cudaGetSymbolAddress((void**)&p_h,    g_h);
    cudaGetSymbolAddress((void**)&p_qkv,  g_qkv);
    cudaGetSymbolAddress((void**)&p_qh,   g_qkvh);
    cudaGetSymbolAddress((void**)&p_ql,   g_qkvl);
    cudaGetSymbolAddress((void**)&p_nh,   g_normh);
    cudaGetSymbolAddress((void**)&p_nl,   g_norml);
    cudaGetSymbolAddress((void**)&p_ch,   g_ctxh);
    cudaGetSymbolAddress((void**)&p_cl,   g_ctxl);
    cudaGetSymbolAddress((void**)&p_ah,   g_acth);
    cudaGetSymbolAddress((void**)&p_al,   g_actl);
    cudaGetSymbolAddress((void**)&p_wqh,  g_wqkvh);
    cudaGetSymbolAddress((void**)&p_wql,  g_wqkvl);
    cudaGetSymbolAddress((void**)&p_woh,  g_woh);
    cudaGetSymbolAddress((void**)&p_wol,  g_wol);
    cudaGetSymbolAddress((void**)&p_wuh,  g_wuph);
    cudaGetSymbolAddress((void**)&p_wul,  g_wupl);
    cudaGetSymbolAddress((void**)&p_wdh,  g_wdnh);
    cudaGetSymbolAddress((void**)&p_wdl,  g_wdnl);

    cudaFuncSetAttribute(hgemm<0>, cudaFuncAttributeMaxDynamicSharedMemorySize, GEMM_SMEM_BYTES);
    cudaFuncSetAttribute(hgemm<1>, cudaFuncAttributeMaxDynamicSharedMemorySize, GEMM_SMEM_BYTES);
    cudaFuncSetAttribute(hgemm<2>, cudaFuncAttributeMaxDynamicSharedMemorySize, GEMM_SMEM_BYTES);
    cudaFuncSetAttribute(attn_kernel, cudaFuncAttributeMaxDynamicSharedMemorySize, ATT_SMEM);

    const int TM = T_TOK / 128;
    dim3 wblk(32, 8);

    // 0) weight transpose + split
    wsplit_kernel<<<dim3(QKV_N / 32, HID / 64), wblk>>>(w_qkv, p_wqh, p_wql, HID, QKV_N);
    wsplit_kernel<<<dim3(HID / 32, HID / 64), wblk>>>(w_o, p_woh, p_wol, HID, HID);
    wsplit_kernel<<<dim3(UP_N / 32, HID / 64), wblk>>>(w_up, p_wuh, p_wul, HID, UP_N);
    wsplit_kernel<<<dim3(HID / 32, INTER / 64), wblk>>>(w_down, p_wdh, p_wdl, INTER, HID);

    // 1) h = hs + res ; norm1 planes = LN1(h)
    ln_kernel<<<T_TOK, 256>>>(hs, res, w_ln1, b_ln1, p_h, p_nh, p_nl);

    // 2) qkv = norm1 @ w_qkv + b_qkv
    hgemm<0><<<TM * (QKV_N / 256), 320, GEMM_SMEM_BYTES>>>(
        p_nh, p_nl, p_wqh, p_wql, b_qkv, nullptr, p_qkv, nullptr, nullptr,
        QKV_N, HID, QKV_N / 256);

    // 3) RoPE in place, then split to bf16 planes (Q pre-scaled)
    rope_kernel<<<T_TOK, 256>>>(p_qkv, cosp, sinp);
    qkvsplit_kernel<<<T_TOK, 256>>>(p_qkv, p_qh, p_ql);

    // 4) HMMA flash attention -> ctx planes
    attn_kernel<<<dim3(SEQ / 64, NH, BATCH), 128, ATT_SMEM>>>(p_qh, p_ql, p_ch, p_cl);

    // 5) h2 = ctx @ w_o + h
    hgemm<1><<<TM * (HID / 256), 320, GEMM_SMEM_BYTES>>>(
        p_ch, p_cl, p_woh, p_wol, nullptr, p_h, h2, nullptr, nullptr,
        HID, HID, HID / 256);

    // 6) norm2 planes = LN2(h2)
    ln_kernel<<<T_TOK, 256>>>(h2, nullptr, w_ln2, b_ln2, nullptr, p_nh, p_nl);

    // 7) act planes = gegelu(norm2 @ w_up + b_up)
    hgemm<2><<<TM * (UP_N / 256), 320, GEMM_SMEM_BYTES>>>(
        p_nh, p_nl, p_wuh, p_wul, b_up, nullptr, nullptr, p_ah, p_al,
        UP_N, HID, UP_N / 256);

    // 8) mlp_out = act @ w_down + b_down
    hgemm<0><<<TM * (HID / 256), 320, GEMM_SMEM_BYTES>>>(
        p_ah, p_al, p_wdh, p_wdl, b_down, nullptr, mlp_out, nullptr, nullptr,
        HID, INTER, HID / 256);
}

// round 17
// speedup vs baseline: 1.3835x; 1.3835x over previous
#include <cuda_runtime.h>
#include <cuda_bf16.h>
#include <math.h>
#include <stdint.h>

// ---------------- problem constants ----------------
#define T_TOK   4096
#define HID     4096
#define NH      32
#define NKV     8
#define HD      128
#define INTER   14336
#define BATCH   4
#define SEQ     1024
#define QKV_N   6144            // (NH + 2*NKV) * HD
#define UP_N    28672           // 2 * INTER
#define LIMIT   20.0f
#define LN_EPS  1e-5f
#define ATTN_SCALE 0.08838834764831845f  // 128^-0.5

// ---------------- device scratch (no allocations allowed) ----------------
__device__ float g_h[(size_t)T_TOK * HID];
__device__ float g_qkv[(size_t)T_TOK * QKV_N];
// split-bf16 qkv planes (Q pre-scaled by ATTN_SCALE)
__device__ __nv_bfloat16 g_qkvh[(size_t)T_TOK * QKV_N];
__device__ __nv_bfloat16 g_qkvl[(size_t)T_TOK * QKV_N];
// split-bf16 activation planes
__device__ __nv_bfloat16 g_normh[(size_t)T_TOK * HID];
__device__ __nv_bfloat16 g_norml[(size_t)T_TOK * HID];
__device__ __nv_bfloat16 g_ctxh[(size_t)T_TOK * HID];
__device__ __nv_bfloat16 g_ctxl[(size_t)T_TOK * HID];
__device__ __nv_bfloat16 g_acth[(size_t)T_TOK * INTER];
__device__ __nv_bfloat16 g_actl[(size_t)T_TOK * INTER];
// split-bf16 TRANSPOSED weight planes: [N][K]
__device__ __nv_bfloat16 g_wqkvh[(size_t)QKV_N * HID];
__device__ __nv_bfloat16 g_wqkvl[(size_t)QKV_N * HID];
__device__ __nv_bfloat16 g_woh[(size_t)HID * HID];
__device__ __nv_bfloat16 g_wol[(size_t)HID * HID];
__device__ __nv_bfloat16 g_wuph[(size_t)UP_N * HID];
__device__ __nv_bfloat16 g_wupl[(size_t)UP_N * HID];
__device__ __nv_bfloat16 g_wdnh[(size_t)HID * INTER];
__device__ __nv_bfloat16 g_wdnl[(size_t)HID * INTER];

// =======================================================================
// Helpers
// =======================================================================
__device__ __forceinline__ uint32_t swz128(uint32_t o) {
    return o ^ ((o >> 3) & 0x70);
}
__device__ __forceinline__ uint32_t smem_u32(const void* p) {
    uint32_t a;
    asm("{ .reg .u64 t; cvta.to.shared.u64 t, %1; cvt.u32.u64 %0, t; }"
        : "=r"(a) : "l"(p));
    return a;
}
__device__ __forceinline__ void cp16(uint32_t s, const void* g) {
    asm volatile("cp.async.cg.shared.global [%0], [%1], 16;" :: "r"(s), "l"(g));
}
#define CP_COMMIT() asm volatile("cp.async.commit_group;" ::: "memory")
#define CP_WAIT1()  asm volatile("cp.async.wait_group 1;" ::: "memory")
#define CP_WAIT0()  asm volatile("cp.async.wait_group 0;" ::: "memory")

__device__ __forceinline__ void ldsm4(uint32_t* r, uint32_t addr) {
    asm volatile("ldmatrix.sync.aligned.m8n8.x4.shared.b16 {%0,%1,%2,%3}, [%4];"
                 : "=r"(r[0]), "=r"(r[1]), "=r"(r[2]), "=r"(r[3])
                 : "r"(addr));
}
__device__ __forceinline__ void ldsm4t(uint32_t* r, uint32_t addr) {
    asm volatile("ldmatrix.sync.aligned.m8n8.x4.trans.shared.b16 {%0,%1,%2,%3}, [%4];"
                 : "=r"(r[0]), "=r"(r[1]), "=r"(r[2]), "=r"(r[3])
                 : "r"(addr));
}

__device__ __forceinline__ float gegelu_pair(float a_in, float lin_in) {
    float a   = fminf(a_in, LIMIT);
    float lin = fminf(fmaxf(lin_in, -LIMIT), LIMIT);
    float sig = 1.0f / (1.0f + __expf(-1.702f * a));
    return a * sig * (lin + 1.0f);
}
__device__ __forceinline__ void split1(float v, __nv_bfloat16& h, __nv_bfloat16& l) {
    h = __float2bfloat16(v);
    l = __float2bfloat16(v - __bfloat162float(h));
}
__device__ __forceinline__ void split2w(float a, float b, uint32_t& hw, uint32_t& lw) {
    __nv_bfloat162 hv, lv;
    hv.x = __float2bfloat16(a);
    hv.y = __float2bfloat16(b);
    lv.x = __float2bfloat16(a - __bfloat162float(hv.x));
    lv.y = __float2bfloat16(b - __bfloat162float(hv.y));
    hw = *(uint32_t*)&hv;
    lw = *(uint32_t*)&lv;
}
__device__ __forceinline__ uint32_t packbf2(float a, float b) {
    __nv_bfloat162 v;
    v.x = __float2bfloat16(a);
    v.y = __float2bfloat16(b);
    return *(uint32_t*)&v;
}

__device__ __forceinline__ void mma16816(float* c, const uint32_t* a,
                                         const uint32_t* b) {
    asm volatile(
        "mma.sync.aligned.m16n8k16.row.col.f32.bf16.bf16.f32 "
        "{%0,%1,%2,%3}, {%4,%5,%6,%7}, {%8,%9}, {%0,%1,%2,%3};"
        : "+f"(c[0]), "+f"(c[1]), "+f"(c[2]), "+f"(c[3])
        : "r"(a[0]), "r"(a[1]), "r"(a[2]), "r"(a[3]), "r"(b[0]), "r"(b[1]));
}

// =======================================================================
// Weight transpose + split: w [K][N] fp32 -> th, tl [N][K] bf16.
// =======================================================================
__global__ void wsplit_kernel(const float* __restrict__ w,
                              __nv_bfloat16* __restrict__ th,
                              __nv_bfloat16* __restrict__ tl,
                              int K, int N) {
    __shared__ float s[64][33];
    const int k0 = blockIdx.y * 64, n0 = blockIdx.x * 32;
    const int tx = threadIdx.x, ty = threadIdx.y;
#pragma unroll
    for (int i = 0; i < 8; i++) {
        int k = ty + i * 8;
        s[k][tx] = w[(size_t)(k0 + k) * N + n0 + tx];
    }
    __syncthreads();
#pragma unroll
    for (int j = 0; j < 4; j++) {
        int n = ty * 4 + j;
        uint32_t hw, lw;
        split2w(s[tx * 2][n], s[tx * 2 + 1][n], hw, lw);
        size_t o = (size_t)(n0 + n) * K + k0 + tx * 2;
        *(uint32_t*)&th[o] = hw;
        *(uint32_t*)&tl[o] = lw;
    }
}

// =======================================================================
// LayerNorm (optionally fused residual add); writes split-bf16 planes
// =======================================================================
__global__ void ln_kernel(const float* __restrict__ x,
                          const float* __restrict__ res,
                          const float* __restrict__ w,
                          const float* __restrict__ b,
                          float* __restrict__ h_out,
                          __nv_bfloat16* __restrict__ nh,
                          __nv_bfloat16* __restrict__ nl) {
    __shared__ float sred[256];
    const int row = blockIdx.x;
    const int tid = threadIdx.x;
    const size_t base = (size_t)row * HID;

    float vals[16];
    float s = 0.f, s2 = 0.f;
#pragma unroll
    for (int i = 0; i < 16; i++) {
        int c = i * 256 + tid;
        float v = x[base + c];
        if (res)   v += res[base + c];
        if (h_out) h_out[base + c] = v;
        vals[i] = v;
        s += v;
        s2 += v * v;
    }
    sred[tid] = s; __syncthreads();
    for (int off = 128; off > 0; off >>= 1) {
        if (tid < off) sred[tid] += sred[tid + off];
        __syncthreads();
    }
    float mean = sred[0] * (1.0f / HID);
    __syncthreads();
    sred[tid] = s2; __syncthreads();
    for (int off = 128; off > 0; off >>= 1) {
        if (tid < off) sred[tid] += sred[tid + off];
        __syncthreads();
    }
    float var = sred[0] * (1.0f / HID) - mean * mean;
    float rstd = rsqrtf(var + LN_EPS);

#pragma unroll
    for (int i = 0; i < 16; i++) {
        int c = i * 256 + tid;
        float v = (vals[i] - mean) * rstd * w[c] + b[c];
        __nv_bfloat16 h, l;
        split1(v, h, l);
        nh[base + c] = h;
        nl[base + c] = l;
    }
}

// =======================================================================
// Fused RoPE + split: reads fp32 qkv, rotates q/k, scales Q by ATTN_SCALE,
// writes bf16 hi/lo planes directly (fp32 qkv is not written back).
// =======================================================================
__global__ void rope_split_kernel(const float* __restrict__ qkv,
                                  const float* __restrict__ cosp,
                                  const float* __restrict__ sinp,
                                  __nv_bfloat16* __restrict__ qh,
                                  __nv_bfloat16* __restrict__ ql) {
    const int t = blockIdx.x;
    const size_t tb = (size_t)t * QKV_N;
    const float* cr = cosp + (size_t)t * 64;
    const float* sr = sinp + (size_t)t * 64;

    // rotated q/k: (NH + NKV) * 64 = 2560 pairs
    for (int i = threadIdx.x; i < (NH + NKV) * 64; i += 256) {
        int h = i >> 6;
        int d = i & 63;
        size_t base = tb +
            (h < NH ? (size_t)h * HD : (size_t)NH * HD + (size_t)(h - NH) * HD);
        float c = cr[d], s = sr[d];
        float x1 = qkv[base + d];
        float x2 = qkv[base + 64 + d];
        float r1 = x1 * c - x2 * s;
        float r2 = x2 * c + x1 * s;
        float sc = (h < NH) ? ATTN_SCALE : 1.0f;
        r1 *= sc; r2 *= sc;
        __nv_bfloat16 hh, ll;
        split1(r1, hh, ll); qh[base + d] = hh;      ql[base + d] = ll;
        split1(r2, hh, ll); qh[base + 64 + d] = hh; ql[base + 64 + d] = ll;
    }
    // v part: NKV*HD = 1024 elements, no rotation
    for (int i = threadIdx.x; i < NKV * HD; i += 256) {
        size_t base = tb + (size_t)(NH + NKV) * HD + i;
        __nv_bfloat16 hh, ll;
        split1(qkv[base], hh, ll);
        qh[base] = hh;
        ql[base] = ll;
    }
}

// =======================================================================
// HMMA flash attention (causal, GQA). Block = 64 q-rows x 2 heads (same
// kv group), 256 threads (warps 0-3 head 2y, warps 4-7 head 2y+1).
// 64-key tiles, K/V double-buffered cp.async, shared by both heads.
// SMEM: Q head0 @0 (32KB), Q head1 @32K (32KB),
//       KV buf[2]: Kh@0 Kl@16K Vh@32K Vl@48K each, @64K and @128K.
// =======================================================================
#define ATT_SMEM (65536 + 2 * 65536)

__global__ void __launch_bounds__(256, 1) attn_kernel(
        const __nv_bfloat16* __restrict__ qph,
        const __nv_bfloat16* __restrict__ qpl,
        __nv_bfloat16* __restrict__ ctxh,
        __nv_bfloat16* __restrict__ ctxl) {
    extern __shared__ __align__(1024) char smem[];
    const uint32_t sb = smem_u32(smem);
    const int qt  = blockIdx.x;
    const int hp  = blockIdx.y;          // head pair index: heads 2hp, 2hp+1
    const int b   = blockIdx.z;
    const int tid  = threadIdx.x;
    const int wid  = tid >> 5;
    const int lane = tid & 31;
    const int w4   = wid & 3;            // warp within head (q rows w4*16..+15)
    const int hl   = wid >> 2;           // head within block
    const int hq   = hp * 2 + hl;
    const int gid = lane >> 2, tg = lane & 3;
    const int matq = lane >> 3, rowin = lane & 7;

    const int kvh  = hq >> 2;            // same for both heads in block
    const int koff = NH * HD + kvh * HD;
    const int voff = NH * HD + NKV * HD + kvh * HD;
    const size_t bS = (size_t)b * SEQ;

    const uint32_t a_row = (uint32_t)((matq & 1) * 8 + rowin);
    const uint32_t a_ch  = (uint32_t)(matq >> 1);
    const uint32_t b_row = (uint32_t)((matq >> 1) * 8 + rowin);
    const uint32_t b_ch  = (uint32_t)(matq & 1);
    const uint32_t v_row = (uint32_t)((matq & 1) * 8 + rowin);
    const uint32_t v_ch  = (uint32_t)(matq >> 1);

    const uint32_t qbase = sb + hl * 32768;
    const uint32_t kvb0  = sb + 65536;

    // ---- stage Q for both heads: 4096 cp16 over 256 threads ----
#pragma unroll
    for (int q = 0; q < 16; q++) {
        int idx = q * 256 + tid;
        int c = idx & 7, r = (idx >> 3) & 63, h2 = (idx >> 9) & 1;
        int rest = idx >> 10;            // 0..3
        int sel = rest & 1, hh = rest >> 1;
        const __nv_bfloat16* src = sel ? qpl : qph;
        uint32_t dst = sb + hh * 32768 + sel * 16384 + h2 * 8192 +
                       swz128((uint32_t)(r * 128 + c * 16));
        cp16(dst, src + (bS + qt * 64 + r) * QKV_N + (hp * 2 + hh) * HD + h2 * 64 + c * 8);
    }
    // ---- stage KV tile 0 into buf 0: 4096 cp16 ----
#pragma unroll
    for (int q = 0; q < 16; q++) {
        int idx = q * 256 + tid;
        int c = idx & 7, r = (idx >> 3) & 63, h2 = (idx >> 9) & 1, sel = idx >> 10;
        const __nv_bfloat16* src = (sel & 1) ? qpl : qph;
        int colb = (sel < 2 ? koff : voff) + h2 * 64 + c * 8;
        uint32_t dst = kvb0 + sel * 16384 + h2 * 8192 +
                       swz128((uint32_t)(r * 128 + c * 16));
        cp16(dst, src + (bS + r) * QKV_N + colb);
    }
    CP_COMMIT();

    float m0 = -1e30f, m1 = -1e30f, l0 = 0.f, l1 = 0.f;
    float ctx[16][4];
#pragma unroll
    for (int j = 0; j < 16; j++)
#pragma unroll
        for (int q = 0; q < 4; q++) ctx[j][q] = 0.f;

    const int qg0 = qt * 64 + w4 * 16 + gid;
    const int qg1 = qg0 + 8;

#pragma unroll 1
    for (int kt = 0; kt <= qt; kt++) {
        CP_WAIT0();
        __syncthreads();
        const uint32_t bb = kvb0 + (kt & 1) * 65536;
        if (kt < qt) {
            uint32_t nb = kvb0 + ((kt + 1) & 1) * 65536;
#pragma unroll
            for (int q = 0; q < 16; q++) {
                int idx = q * 256 + tid;
                int c = idx & 7, r = (idx >> 3) & 63, h2 = (idx >> 9) & 1, sel = idx >> 10;
                const __nv_bfloat16* src = (sel & 1) ? qpl : qph;
                int colb = (sel < 2 ? koff : voff) + h2 * 64 + c * 8;
                uint32_t dst = nb + sel * 16384 + h2 * 8192 +
                               swz128((uint32_t)(r * 128 + c * 16));
                cp16(dst, src + (bS + (kt + 1) * 64 + r) * QKV_N + colb);
            }
            CP_COMMIT();
        }

        // ---- S = Q K^T (3-term split-bf16) ----
        float sc[8][4];
#pragma unroll
        for (int j = 0; j < 8; j++)
#pragma unroll
            for (int q = 0; q < 4; q++) sc[j][q] = 0.f;

#pragma unroll
        for (int h2 = 0; h2 < 2; h2++) {
#pragma unroll
            for (int kc = 0; kc < 4; kc++) {
                uint32_t arow = (uint32_t)(w4 * 16) + a_row;
                uint32_t offa = h2 * 8192 + swz128(arow * 128 + (2 * kc + a_ch) * 16);
                uint32_t qhf[4], qlf[4];
                ldsm4(qhf, qbase + offa);
                ldsm4(qlf, qbase + 16384 + offa);
                uint32_t khf[8][2], klf[8][2];
#pragma unroll
                for (int g = 0; g < 4; g++) {
                    uint32_t rowb = (uint32_t)(g * 16) + b_row;
                    uint32_t offb = h2 * 8192 + swz128(rowb * 128 + (2 * kc + b_ch) * 16);
                    ldsm4(&khf[2 * g][0], bb + offb);
                    ldsm4(&klf[2 * g][0], bb + 16384 + offb);
                }
#pragma unroll
                for (int j = 0; j < 8; j++) mma16816(sc[j], qhf, khf[j]);
#pragma unroll
                for (int j = 0; j < 8; j++) mma16816(sc[j], qhf, klf[j]);
#pragma unroll
                for (int j = 0; j < 8; j++) mma16816(sc[j], qlf, khf[j]);
            }
        }

        if (kt == qt) {
#pragma unroll
            for (int j = 0; j < 8; j++) {
                int k0 = kt * 64 + j * 8 + tg * 2;
                if (k0     > qg0) sc[j][0] = -1e30f;
                if (k0 + 1 > qg0) sc[j][1] = -1e30f;
                if (k0     > qg1) sc[j][2] = -1e30f;
                if (k0 + 1 > qg1) sc[j][3] = -1e30f;
            }
        }

        float rm0 = -1e30f, rm1 = -1e30f;
#pragma unroll
        for (int j = 0; j < 8; j++) {
            rm0 = fmaxf(rm0, fmaxf(sc[j][0], sc[j][1]));
            rm1 = fmaxf(rm1, fmaxf(sc[j][2], sc[j][3]));
        }
        rm0 = fmaxf(rm0, __shfl_xor_sync(0xffffffffu, rm0, 1));
        rm0 = fmaxf(rm0, __shfl_xor_sync(0xffffffffu, rm0, 2));
        rm1 = fmaxf(rm1, __shfl_xor_sync(0xffffffffu, rm1, 1));
        rm1 = fmaxf(rm1, __shfl_xor_sync(0xffffffffu, rm1, 2));
        float mn0 = fmaxf(m0, rm0), mn1 = fmaxf(m1, rm1);
        float sf0 = __expf(m0 - mn0), sf1 = __expf(m1 - mn1);
        m0 = mn0; m1 = mn1;
        float ps0 = 0.f, ps1 = 0.f;
#pragma unroll
        for (int j = 0; j < 8; j++) {
            sc[j][0] = __expf(sc[j][0] - mn0);
            sc[j][1] = __expf(sc[j][1] - mn0);
            sc[j][2] = __expf(sc[j][2] - mn1);
            sc[j][3] = __expf(sc[j][3] - mn1);
            ps0 += sc[j][0] + sc[j][1];
            ps1 += sc[j][2] + sc[j][3];
        }
        ps0 += __shfl_xor_sync(0xffffffffu, ps0, 1);
        ps0 += __shfl_xor_sync(0xffffffffu, ps0, 2);
        ps1 += __shfl_xor_sync(0xffffffffu, ps1, 1);
        ps1 += __shfl_xor_sync(0xffffffffu, ps1, 2);
        l0 = l0 * sf0 + ps0;
        l1 = l1 * sf1 + ps1;
#pragma unroll
        for (int j = 0; j < 16; j++) {
            ctx[j][0] *= sf0; ctx[j][1] *= sf0;
            ctx[j][2] *= sf1; ctx[j][3] *= sf1;
        }

        uint32_t pah[4][4], pal[4][4];
#pragma unroll
        for (int t = 0; t < 4; t++) {
#pragma unroll
            for (int half = 0; half < 2; half++) {
                int j = 2 * t + half;
                float p0 = sc[j][0], p1 = sc[j][1], p2 = sc[j][2], p3 = sc[j][3];
                __nv_bfloat16 h0 = __float2bfloat16(p0), h1 = __float2bfloat16(p1);
                __nv_bfloat16 h2 = __float2bfloat16(p2), h3 = __float2bfloat16(p3);
                pah[t][half * 2 + 0] = ((uint32_t)*(uint16_t*)&h1 << 16) | *(uint16_t*)&h0;
                pah[t][half * 2 + 1] = ((uint32_t)*(uint16_t*)&h3 << 16) | *(uint16_t*)&h2;
                pal[t][half * 2 + 0] = packbf2(p0 - __bfloat162float(h0),
                                               p1 - __bfloat162float(h1));
                pal[t][half * 2 + 1] = packbf2(p2 - __bfloat162float(h2),
                                               p3 - __bfloat162float(h3));
            }
        }

#pragma unroll
        for (int t = 0; t < 4; t++) {
#pragma unroll
            for (int g = 0; g < 8; g++) {
                uint32_t vr = (uint32_t)(t * 16) + v_row;
                uint32_t vc = (uint32_t)((g & 3) * 2) + v_ch;
                uint32_t offv = (g >> 2) * 8192 + swz128(vr * 128 + vc * 16);
                uint32_t vhf[4], vlf[4];
                ldsm4t(vhf, bb + 32768 + offv);
                ldsm4t(vlf, bb + 49152 + offv);
                mma16816(ctx[2 * g],     pah[t], vhf);
                mma16816(ctx[2 * g],     pah[t], vlf);
                mma16816(ctx[2 * g],     pal[t], vhf);
                mma16816(ctx[2 * g + 1], pah[t], vhf + 2);
                mma16816(ctx[2 * g + 1], pah[t], vlf + 2);
                mma16816(ctx[2 * g + 1], pal[t], vhf + 2);
            }
        }
        __syncthreads();
    }

    float inv0 = 1.0f / l0, inv1 = 1.0f / l1;
    const size_t t0 = (bS + qt * 64 + w4 * 16 + gid) * (size_t)HID + hq * HD;
    const size_t t1 = t0 + (size_t)8 * HID;
#pragma unroll
    for (int j = 0; j < 16; j++) {
        int col = j * 8 + tg * 2;
        float v0 = ctx[j][0] * inv0, v1 = ctx[j][1] * inv0;
        float v2 = ctx[j][2] * inv1, v3 = ctx[j][3] * inv1;
        uint32_t hw, lw;
        split2w(v0, v1, hw, lw);
        *(uint32_t*)&ctxh[t0 + col] = hw;
        *(uint32_t*)&ctxl[t0 + col] = lw;
        split2w(v2, v3, hw, lw);
        *(uint32_t*)&ctxh[t1 + col] = hw;
        *(uint32_t*)&ctxl[t1 + col] = lw;
    }
}

// =======================================================================
// HMMA split-bf16 GEMM (exact R14). CTA 128x256, K-chunk 64, PIPE=2
// (96KB/stage), 256 threads, warp tile m32 x n128.
// =======================================================================
#define PIPE 2
#define STAGE_BYTES 98304
#define GEMM_SMEM_BYTES (PIPE * STAGE_BYTES)

__device__ __forceinline__ void stage_issue(uint32_t st,
                                            const __nv_bfloat16* __restrict__ Ah,
                                            const __nv_bfloat16* __restrict__ Al,
                                            const __nv_bfloat16* __restrict__ Bh,
                                            const __nv_bfloat16* __restrict__ Bl,
                                            int bm, int bn, int kt, int K, int tid) {
#pragma unroll
    for (int q = 0; q < 4; q++) {
        int idx = q * 256 + tid;
        int r = idx >> 3, c = idx & 7;
        uint32_t off = swz128((uint32_t)(r * 128 + c * 16));
        size_t ga = (size_t)(bm * 128 + r) * K + kt * 64 + c * 8;
        cp16(st + off,         Ah + ga);
        cp16(st + 16384 + off, Al + ga);
    }
#pragma unroll
    for (int q = 0; q < 8; q++) {
        int idx = q * 256 + tid;
        int r = idx >> 3, c = idx & 7;
        uint32_t off = swz128((uint32_t)(r * 128 + c * 16));
        size_t gb = (size_t)(bn * 256 + r) * K + kt * 64 + c * 8;
        cp16(st + 32768 + off, Bh + gb);
        cp16(st + 65536 + off, Bl + gb);
    }
}

template <int EPI>
__global__ void __launch_bounds__(256, 1) hgemm(const __nv_bfloat16* __restrict__ Ah,
                                                const __nv_bfloat16* __restrict__ Al,
                                                const __nv_bfloat16* __restrict__ Bh,
                                                const __nv_bfloat16* __restrict__ Bl,
                                                const float* __restrict__ bias,
                                                const float* __restrict__ addsrc,
                                                float* __restrict__ C,
                                                __nv_bfloat16* __restrict__ Ch,
                                                __nv_bfloat16* __restrict__ Cl,
                                                int N, int K, int tiles_n) {
    extern __shared__ __align__(1024) char smem[];
    const uint32_t sb = smem_u32(smem);
    const int tid  = threadIdx.x;
    const int wid  = tid >> 5;
    const int lane = tid & 31;

    const int lin = blockIdx.x;
    const int per = 8 * tiles_n;
    const int grp = lin / per, rem = lin % per;
    const int bm = grp * 8 + (rem & 7);
    const int bn = rem >> 3;

    const int KT = K >> 6;

    const int wm = (wid >> 1) * 32;
    const int wn = (wid & 1) * 128;
    const int gid = lane >> 2, tg = lane & 3;

    const int matq  = lane >> 3;
    const int rowin = lane & 7;
    const uint32_t a_row = (uint32_t)((matq & 1) * 8 + rowin);
    const uint32_t a_ch  = (uint32_t)(matq >> 1);
    const uint32_t b_row = (uint32_t)((matq >> 1) * 8 + rowin);
    const uint32_t b_ch  = (uint32_t)(matq & 1);

    float acc[2][16][4];
#pragma unroll
    for (int mi = 0; mi < 2; mi++)
#pragma unroll
        for (int ni = 0; ni < 16; ni++)
#pragma unroll
            for (int q = 0; q < 4; q++) acc[mi][ni][q] = 0.f;

    stage_issue(sb, Ah, Al, Bh, Bl, bm, bn, 0, K, tid);
    CP_COMMIT();
    stage_issue(sb + STAGE_BYTES, Ah, Al, Bh, Bl, bm, bn, 1, K, tid);
    CP_COMMIT();

#pragma unroll 1
    for (int kt = 0; kt < KT; kt++) {
        CP_WAIT1();
        __syncthreads();

        const uint32_t st = sb + (kt & 1) * STAGE_BYTES;
#pragma unroll
        for (int ks = 0; ks < 4; ks++) {
            const uint32_t kc = (uint32_t)(ks * 2);
            uint32_t ahf[2][4], alf[2][4];
#pragma unroll
            for (int mi = 0; mi < 2; mi++) {
                uint32_t row = (uint32_t)(wm + mi * 16) + a_row;
                uint32_t off = swz128(row * 128 + (kc + a_ch) * 16);
                ldsm4(ahf[mi], st + off);
                ldsm4(alf[mi], st + 16384 + off);
            }
#pragma unroll
            for (int bh2 = 0; bh2 < 2; bh2++) {
                uint32_t bhf[8][2], blf[8][2];
#pragma unroll
                for (int q = 0; q < 4; q++) {
                    uint32_t row = (uint32_t)(wn + bh2 * 64 + q * 16) + b_row;
                    uint32_t off = swz128(row * 128 + (kc + b_ch) * 16);
                    ldsm4(&bhf[2 * q][0], st + 32768 + off);
                    ldsm4(&blf[2 * q][0], st + 65536 + off);
                }
#pragma unroll
                for (int mi = 0; mi < 2; mi++)
#pragma unroll
                    for (int ni = 0; ni < 8; ni++)
                        mma16816(acc[mi][bh2 * 8 + ni], ahf[mi], bhf[ni]);
#pragma unroll
                for (int mi = 0; mi < 2; mi++)
#pragma unroll
                    for (int ni = 0; ni < 8; ni++)
                        mma16816(acc[mi][bh2 * 8 + ni], ahf[mi], blf[ni]);
#pragma unroll
                for (int mi = 0; mi < 2; mi++)
#pragma unroll
                    for (int ni = 0; ni < 8; ni++)
                        mma16816(acc[mi][bh2 * 8 + ni], alf[mi], bhf[ni]);
            }
        }

        if (kt + 2 < KT) {
            __syncthreads();
            stage_issue(st, Ah, Al, Bh, Bl, bm, bn, kt + 2, K, tid);
            CP_COMMIT();
        }
    }

#pragma unroll
    for (int mi = 0; mi < 2; mi++) {
#pragma unroll
        for (int ni = 0; ni < 16; ni++) {
            int row0 = bm * 128 + wm + mi * 16 + gid;
            int row1 = row0 + 8;
            int col  = bn * 256 + wn + ni * 8 + tg * 2;
            float c0 = acc[mi][ni][0], c1 = acc[mi][ni][1];
            float c2 = acc[mi][ni][2], c3 = acc[mi][ni][3];
            if (EPI == 2) {
                float b0 = bias[col], b1 = bias[col + 1];
                float v0 = gegelu_pair(c0 + b0, c1 + b1);
                float v1 = gegelu_pair(c2 + b0, c3 + b1);
                size_t o0 = (size_t)row0 * (N >> 1) + (col >> 1);
                size_t o1 = (size_t)row1 * (N >> 1) + (col >> 1);
                __nv_bfloat16 h, l;
                split1(v0, h, l); Ch[o0] = h; Cl[o0] = l;
                split1(v1, h, l); Ch[o1] = h; Cl[o1] = l;
            } else if (EPI == 0) {
                float b0 = bias[col], b1 = bias[col + 1];
                *(float2*)(C + (size_t)row0 * N + col) = make_float2(c0 + b0, c1 + b1);
                *(float2*)(C + (size_t)row1 * N + col) = make_float2(c2 + b0, c3 + b1);
            } else {
                float2 a0 = *(const float2*)(addsrc + (size_t)row0 * N + col);
                float2 a1 = *(const float2*)(addsrc + (size_t)row1 * N + col);
                *(float2*)(C + (size_t)row0 * N + col) = make_float2(c0 + a0.x, c1 + a0.y);
                *(float2*)(C + (size_t)row1 * N + col) = make_float2(c2 + a1.x, c3 + a1.y);
            }
        }
    }
}

// =======================================================================
// launcher
// =======================================================================
extern "C" void kernel_launch(void* const* d_in, const int* in_sizes, int n_in,
                              void* d_out, int out_size) {
    const float* hs     = (const float*)d_in[0];
    const float* res    = (const float*)d_in[1];
    const float* cosp   = (const float*)d_in[2];
    const float* sinp   = (const float*)d_in[3];
    const float* w_qkv  = (const float*)d_in[5];
    const float* b_qkv  = (const float*)d_in[6];
    const float* w_o    = (const float*)d_in[7];
    const float* w_ln1  = (const float*)d_in[8];
    const float* b_ln1  = (const float*)d_in[9];
    const float* w_ln2  = (const float*)d_in[10];
    const float* b_ln2  = (const float*)d_in[11];
    const float* w_up   = (const float*)d_in[12];
    const float* b_up   = (const float*)d_in[13];
    const float* w_down = (const float*)d_in[14];
    const float* b_down = (const float*)d_in[15];

    float* out     = (float*)d_out;
    float* mlp_out = out;
    float* h2      = out + (size_t)T_TOK * HID;

    float *p_h, *p_qkv;
    __nv_bfloat16 *p_qh, *p_ql, *p_nh, *p_nl, *p_ch, *p_cl, *p_ah, *p_al;
    __nv_bfloat16 *p_wqh, *p_wql, *p_woh, *p_wol, *p_wuh, *p_wul, *p_wdh, *p_wdl;
    cudaGetSymbolAddress((void**)&p_h,    g_h);
    cudaGetSymbolAddress((void**)&p_qkv,  g_qkv);
    cudaGetSymbolAddress((void**)&p_qh,   g_qkvh);
    cudaGetSymbolAddress((void**)&p_ql,   g_qkvl);
    cudaGetSymbolAddress((void**)&p_nh,   g_normh);
    cudaGetSymbolAddress((void**)&p_nl,   g_norml);
    cudaGetSymbolAddress((void**)&p_ch,   g_ctxh);
    cudaGetSymbolAddress((void**)&p_cl,   g_ctxl);
    cudaGetSymbolAddress((void**)&p_ah,   g_acth);
    cudaGetSymbolAddress((void**)&p_al,   g_actl);
    cudaGetSymbolAddress((void**)&p_wqh,  g_wqkvh);
    cudaGetSymbolAddress((void**)&p_wql,  g_wqkvl);
    cudaGetSymbolAddress((void**)&p_woh,  g_woh);
    cudaGetSymbolAddress((void**)&p_wol,  g_wol);
    cudaGetSymbolAddress((void**)&p_wuh,  g_wuph);
    cudaGetSymbolAddress((void**)&p_wul,  g_wupl);
    cudaGetSymbolAddress((void**)&p_wdh,  g_wdnh);
    cudaGetSymbolAddress((void**)&p_wdl,  g_wdnl);

    cudaFuncSetAttribute(hgemm<0>, cudaFuncAttributeMaxDynamicSharedMemorySize, GEMM_SMEM_BYTES);
    cudaFuncSetAttribute(hgemm<1>, cudaFuncAttributeMaxDynamicSharedMemorySize, GEMM_SMEM_BYTES);
    cudaFuncSetAttribute(hgemm<2>, cudaFuncAttributeMaxDynamicSharedMemorySize, GEMM_SMEM_BYTES);
    cudaFuncSetAttribute(attn_kernel, cudaFuncAttributeMaxDynamicSharedMemorySize, ATT_SMEM);

    const int TM = T_TOK / 128;
    dim3 wblk(32, 8);

    // 0) weight transpose + split
    wsplit_kernel<<<dim3(QKV_N / 32, HID / 64), wblk>>>(w_qkv, p_wqh, p_wql, HID, QKV_N);
    wsplit_kernel<<<dim3(HID / 32, HID / 64), wblk>>>(w_o, p_woh, p_wol, HID, HID);
    wsplit_kernel<<<dim3(UP_N / 32, HID / 64), wblk>>>(w_up, p_wuh, p_wul, HID, UP_N);
    wsplit_kernel<<<dim3(HID / 32, INTER / 64), wblk>>>(w_down, p_wdh, p_wdl, INTER, HID);

    // 1) h = hs + res ; norm1 planes = LN1(h)
    ln_kernel<<<T_TOK, 256>>>(hs, res, w_ln1, b_ln1, p_h, p_nh, p_nl);

    // 2) qkv = norm1 @ w_qkv + b_qkv
    hgemm<0><<<TM * (QKV_N / 256), 256, GEMM_SMEM_BYTES>>>(
        p_nh, p_nl, p_wqh, p_wql, b_qkv, nullptr, p_qkv, nullptr, nullptr,
        QKV_N, HID, QKV_N / 256);

    // 3) fused RoPE + split to bf16 planes (Q pre-scaled)
    rope_split_kernel<<<T_TOK, 256>>>(p_qkv, cosp, sinp, p_qh, p_ql);

    // 4) HMMA flash attention (2 heads/block) -> ctx planes
    attn_kernel<<<dim3(SEQ / 64, NH / 2, BATCH), 256, ATT_SMEM>>>(p_qh, p_ql, p_ch, p_cl);

    // 5) h2 = ctx @ w_o + h
    hgemm<1><<<TM * (HID / 256), 256, GEMM_SMEM_BYTES>>>(
        p_ch, p_cl, p_woh, p_wol, nullptr, p_h, h2, nullptr, nullptr,
        HID, HID, HID / 256);

    // 6) norm2 planes = LN2(h2)
    ln_kernel<<<T_TOK, 256>>>(h2, nullptr, w_ln2, b_ln2, nullptr, p_nh, p_nl);

    // 7) act planes = gegelu(norm2 @ w_up + b_up)
    hgemm<2><<<TM * (UP_N / 256), 256, GEMM_SMEM_BYTES>>>(
        p_nh, p_nl, p_wuh, p_wul, b_up, nullptr, nullptr, p_ah, p_al,
        UP_N, HID, UP_N / 256);

    // 8) mlp_out = act @ w_down + b_down
    hgemm<0><<<TM * (HID / 256), 256, GEMM_SMEM_BYTES>>>(
        p_ah, p_al, p_wdh, p_wdl, b_down, nullptr, mlp_out, nullptr, nullptr,
        HID, INTER, HID / 256);
}